// round 1
// baseline (speedup 1.0000x reference)
#include <cuda_runtime.h>
#include <cstdint>

#define BATCH 256
#define TSTEPS 1024
#define HID 64
#define GATES 256   // 4*HID
#define DIN 3

// Scratch (device globals are the sanctioned scratch path — no cudaMalloc).
__device__ float g_h1[BATCH * TSTEPS * HID];
__device__ float g_h2[BATCH * TSTEPS * HID];

typedef unsigned long long u64;

// ---- packed fp32x2 helpers (sm_100+ only; ptxas never auto-emits these) ----
__device__ __forceinline__ u64 fma2(u64 a, u64 b, u64 c) {
    u64 d; asm("fma.rn.f32x2 %0, %1, %2, %3;" : "=l"(d) : "l"(a), "l"(b), "l"(c)); return d;
}
__device__ __forceinline__ u64 add2(u64 a, u64 b) {
    u64 d; asm("add.rn.f32x2 %0, %1, %2;" : "=l"(d) : "l"(a), "l"(b)); return d;
}
__device__ __forceinline__ u64 packf2(float lo, float hi) {
    u64 d; asm("mov.b64 %0, {%1, %2};" : "=l"(d) : "f"(lo), "f"(hi)); return d;
}
__device__ __forceinline__ float2 unpackf2(u64 v) {
    float2 f; asm("mov.b64 {%0, %1}, %2;" : "=f"(f.x), "=f"(f.y) : "l"(v)); return f;
}
// 16B shared load straight into two 64-bit regs (avoids pack MOVs)
__device__ __forceinline__ void lds2(u64 &a, u64 &b, uint32_t addr) {
    asm volatile("ld.shared.v2.b64 {%0, %1}, [%2];" : "=l"(a), "=l"(b) : "r"(addr));
}

__device__ __forceinline__ float sigf(float x) {
    float e = __expf(-x);
    return __fdividef(1.0f, 1.0f + e);
}
__device__ __forceinline__ float tanhf_(float x) {
    // overflow-safe: exp argument always <= 0
    float ax = fabsf(x);
    float e = __expf(-2.0f * ax);
    float r = __fdividef(1.0f - e, 1.0f + e);
    return copysignf(r, x);
}

// ============================================================================
// Layer 1: one CTA per 2 sequences. Thread j = gate row j (i/f/g/o by j>>6).
// W_hh row in 32 packed u64 regs; h broadcast from shared; c in regs of
// threads 0..127. Input contribution is 3 FMAs from staged x.
// ============================================================================
__global__ void __launch_bounds__(256, 1) lstm_l1(
    const float* __restrict__ x, const float* __restrict__ Wih,
    const float* __restrict__ Whh, const float* __restrict__ bih,
    const float* __restrict__ bhh)
{
    __shared__ __align__(16) float sx[2][TSTEPS * DIN];  // 24 KB
    __shared__ __align__(16) float sh[2][HID];
    __shared__ __align__(16) float sg[2][GATES];
    const int tid = threadIdx.x;
    const int b0 = blockIdx.x * 2;

    // stage both sequences' inputs (3072 floats each)
    {
        const float4* xs0 = (const float4*)(x + (size_t)b0 * TSTEPS * DIN);
        const float4* xs1 = (const float4*)(x + (size_t)(b0 + 1) * TSTEPS * DIN);
        #pragma unroll
        for (int i = 0; i < 3; i++) {
            int idx = tid + i * 256;
            ((float4*)sx[0])[idx] = xs0[idx];
            ((float4*)sx[1])[idx] = xs1[idx];
        }
    }

    // recurrent weights: row j packed as f32x2 pairs along k
    u64 w[32];
    {
        const float4* wr = (const float4*)(Whh + tid * HID);
        #pragma unroll
        for (int i = 0; i < 16; i++) {
            float4 v = wr[i];
            w[2 * i]     = packf2(v.x, v.y);
            w[2 * i + 1] = packf2(v.z, v.w);
        }
    }
    const float wx0 = Wih[tid * 3 + 0], wx1 = Wih[tid * 3 + 1], wx2 = Wih[tid * 3 + 2];
    const float bias = bih[tid] + bhh[tid];
    const int gtype = tid >> 6;

    if (tid < 128) sh[tid >> 6][tid & 63] = 0.0f;
    float c = 0.0f;
    const uint32_t sh0a = (uint32_t)__cvta_generic_to_shared(&sh[0][0]);
    const uint32_t sh1a = (uint32_t)__cvta_generic_to_shared(&sh[1][0]);
    float* outp = &g_h1[(size_t)b0 * TSTEPS * HID];
    __syncthreads();

    #pragma unroll 1
    for (int t = 0; t < TSTEPS; t++) {
        u64 a0 = 0, a1 = 0, a2 = 0, a3 = 0;
        #pragma unroll
        for (int kk = 0; kk < 16; kk++) {
            u64 p0, p1, q0, q1;
            lds2(p0, p1, sh0a + kk * 16);
            lds2(q0, q1, sh1a + kk * 16);
            a0 = fma2(w[2 * kk],     p0, a0);
            a1 = fma2(w[2 * kk + 1], p1, a1);
            a2 = fma2(w[2 * kk],     q0, a2);
            a3 = fma2(w[2 * kk + 1], q1, a3);
        }
        float2 r0 = unpackf2(add2(a0, a1));
        float2 r1 = unpackf2(add2(a2, a3));
        float xa0 = sx[0][t * 3 + 0], xa1 = sx[0][t * 3 + 1], xa2 = sx[0][t * 3 + 2];
        float xb0 = sx[1][t * 3 + 0], xb1 = sx[1][t * 3 + 1], xb2 = sx[1][t * 3 + 2];
        float pre0 = r0.x + r0.y + bias + wx0 * xa0 + wx1 * xa1 + wx2 * xa2;
        float pre1 = r1.x + r1.y + bias + wx0 * xb0 + wx1 * xb1 + wx2 * xb2;
        float v0, v1;
        if (gtype == 2) { v0 = tanhf_(pre0); v1 = tanhf_(pre1); }
        else            { v0 = sigf(pre0);   v1 = sigf(pre1);   }
        sg[0][tid] = v0;
        sg[1][tid] = v1;
        __syncthreads();
        if (tid < 128) {
            const int bb = tid >> 6, m = tid & 63;
            const float* Gp = sg[bb];
            float iv = Gp[m], fv = Gp[m + 64], gv = Gp[m + 128], ov = Gp[m + 192];
            c = fv * c + iv * gv;
            float hn = ov * tanhf_(c);
            sh[bb][m] = hn;
            outp[(size_t)bb * TSTEPS * HID + (size_t)t * HID + m] = hn;
        }
        __syncthreads();
    }
}

// ============================================================================
// Layer 2: same structure, input GEMV (W_ih1 · h1[t]) fused. h1 prefetched one
// step ahead through a shared double buffer (LDG latency off critical path).
// ============================================================================
__global__ void __launch_bounds__(256, 1) lstm_l2(
    const float* __restrict__ Wih, const float* __restrict__ Whh,
    const float* __restrict__ bih, const float* __restrict__ bhh)
{
    __shared__ __align__(16) float sin_[2][2][HID];  // [buf][batch][k]
    __shared__ __align__(16) float sh[2][HID];
    __shared__ __align__(16) float sg[2][GATES];
    const int tid = threadIdx.x;
    const int b0 = blockIdx.x * 2;

    u64 wi[32], wh[32];
    {
        const float4* wr = (const float4*)(Wih + tid * HID);
        const float4* hr = (const float4*)(Whh + tid * HID);
        #pragma unroll
        for (int i = 0; i < 16; i++) {
            float4 v = wr[i]; wi[2 * i] = packf2(v.x, v.y); wi[2 * i + 1] = packf2(v.z, v.w);
            float4 u = hr[i]; wh[2 * i] = packf2(u.x, u.y); wh[2 * i + 1] = packf2(u.z, u.w);
        }
    }
    const float bias = bih[tid] + bhh[tid];
    const int gtype = tid >> 6;

    if (tid < 128) sh[tid >> 6][tid & 63] = 0.0f;
    const float* inbase = &g_h1[(size_t)b0 * TSTEPS * HID];
    if (tid < 32) {  // preload h1[t=0] for both batches
        int bb = tid >> 4, q = tid & 15;
        float4 v = *(const float4*)(inbase + (size_t)bb * TSTEPS * HID + q * 4);
        *(float4*)&sin_[0][bb][q * 4] = v;
    }
    float c = 0.0f;
    const uint32_t sh0a = (uint32_t)__cvta_generic_to_shared(&sh[0][0]);
    const uint32_t sh1a = (uint32_t)__cvta_generic_to_shared(&sh[1][0]);
    const uint32_t sib  = (uint32_t)__cvta_generic_to_shared(&sin_[0][0][0]);
    float* outp = &g_h2[(size_t)b0 * TSTEPS * HID];
    __syncthreads();

    #pragma unroll 1
    for (int t = 0; t < TSTEPS; t++) {
        float4 nxt;
        if (tid < 32) {  // issue prefetch for t+1 early
            int bb = tid >> 4, q = tid & 15;
            int tn = (t + 1 < TSTEPS) ? (t + 1) : t;
            nxt = *(const float4*)(inbase + (size_t)bb * TSTEPS * HID + (size_t)tn * HID + q * 4);
        }
        const int cur = t & 1;
        const uint32_t si0 = sib + cur * (2 * HID * 4);
        const uint32_t si1 = si0 + HID * 4;
        u64 a0 = 0, a1 = 0, a2 = 0, a3 = 0, c0 = 0, c1 = 0, c2 = 0, c3 = 0;
        #pragma unroll
        for (int kk = 0; kk < 16; kk++) {
            u64 p0, p1;
            lds2(p0, p1, si0 + kk * 16);
            a0 = fma2(wi[2 * kk], p0, a0); a1 = fma2(wi[2 * kk + 1], p1, a1);
            lds2(p0, p1, sh0a + kk * 16);
            a2 = fma2(wh[2 * kk], p0, a2); a3 = fma2(wh[2 * kk + 1], p1, a3);
            lds2(p0, p1, si1 + kk * 16);
            c0 = fma2(wi[2 * kk], p0, c0); c1 = fma2(wi[2 * kk + 1], p1, c1);
            lds2(p0, p1, sh1a + kk * 16);
            c2 = fma2(wh[2 * kk], p0, c2); c3 = fma2(wh[2 * kk + 1], p1, c3);
        }
        float2 r0 = unpackf2(add2(add2(a0, a1), add2(a2, a3)));
        float2 r1 = unpackf2(add2(add2(c0, c1), add2(c2, c3)));
        float pre0 = r0.x + r0.y + bias;
        float pre1 = r1.x + r1.y + bias;
        float v0, v1;
        if (gtype == 2) { v0 = tanhf_(pre0); v1 = tanhf_(pre1); }
        else            { v0 = sigf(pre0);   v1 = sigf(pre1);   }
        sg[0][tid] = v0;
        sg[1][tid] = v1;
        if (tid < 32) {  // park prefetched h1[t+1] in the other buffer
            int bb = tid >> 4, q = tid & 15;
            *(float4*)&sin_[cur ^ 1][bb][q * 4] = nxt;
        }
        __syncthreads();
        if (tid < 128) {
            const int bb = tid >> 6, m = tid & 63;
            const float* Gp = sg[bb];
            float iv = Gp[m], fv = Gp[m + 64], gv = Gp[m + 128], ov = Gp[m + 192];
            c = fv * c + iv * gv;
            float hn = ov * tanhf_(c);
            sh[bb][m] = hn;
            outp[(size_t)bb * TSTEPS * HID + (size_t)t * HID + m] = hn;
        }
        __syncthreads();
    }
}

// ============================================================================
// Output projection: y[r, 0..2] = W_out · h2[r] + b_out. 16 lanes per row,
// fully coalesced float4 reads, shuffle reduction.
// ============================================================================
__global__ void __launch_bounds__(256) proj_kernel(
    const float* __restrict__ Wout, const float* __restrict__ bout,
    float* __restrict__ y)
{
    __shared__ float sw[3 * 64];
    __shared__ float sb[3];
    const int tid = threadIdx.x;
    if (tid < 192) sw[tid] = Wout[tid];
    if (tid < 3)   sb[tid] = bout[tid];
    __syncthreads();

    int g = blockIdx.x * 256 + tid;
    int r = g >> 4;
    int seg = g & 15;
    float4 v = *(const float4*)&g_h2[(size_t)r * HID + seg * 4];
    int s4 = seg * 4;
    float a0 = sw[s4] * v.x + sw[s4 + 1] * v.y + sw[s4 + 2] * v.z + sw[s4 + 3] * v.w;
    float a1 = sw[64 + s4] * v.x + sw[64 + s4 + 1] * v.y + sw[64 + s4 + 2] * v.z + sw[64 + s4 + 3] * v.w;
    float a2 = sw[128 + s4] * v.x + sw[128 + s4 + 1] * v.y + sw[128 + s4 + 2] * v.z + sw[128 + s4 + 3] * v.w;
    #pragma unroll
    for (int o = 8; o > 0; o >>= 1) {
        a0 += __shfl_xor_sync(0xffffffffu, a0, o);
        a1 += __shfl_xor_sync(0xffffffffu, a1, o);
        a2 += __shfl_xor_sync(0xffffffffu, a2, o);
    }
    if (seg == 0) {
        y[(size_t)r * 3 + 0] = a0 + sb[0];
        y[(size_t)r * 3 + 1] = a1 + sb[1];
        y[(size_t)r * 3 + 2] = a2 + sb[2];
    }
}

extern "C" void kernel_launch(void* const* d_in, const int* in_sizes, int n_in,
                              void* d_out, int out_size)
{
    const float* x    = (const float*)d_in[0];
    const float* Wih0 = (const float*)d_in[1];
    const float* Whh0 = (const float*)d_in[2];
    const float* bih0 = (const float*)d_in[3];
    const float* bhh0 = (const float*)d_in[4];
    const float* Wih1 = (const float*)d_in[5];
    const float* Whh1 = (const float*)d_in[6];
    const float* bih1 = (const float*)d_in[7];
    const float* bhh1 = (const float*)d_in[8];
    const float* Wout = (const float*)d_in[9];
    const float* bout = (const float*)d_in[10];
    float* y = (float*)d_out;

    lstm_l1<<<BATCH / 2, 256>>>(x, Wih0, Whh0, bih0, bhh0);
    lstm_l2<<<BATCH / 2, 256>>>(Wih1, Whh1, bih1, bhh1);
    proj_kernel<<<(BATCH * TSTEPS * 16) / 256, 256>>>(Wout, bout, y);
}

// round 2
// speedup vs baseline: 1.4561x; 1.4561x over previous
#include <cuda_runtime.h>
#include <cstdint>

#define BATCH 256
#define TSTEPS 1024
#define HID 64
#define DIN 3

// Scratch: only h2 needed now (layer fusion keeps h1 in shared).
__device__ float g_h2[BATCH * TSTEPS * HID];

typedef unsigned long long u64;

// ---- packed fp32x2 helpers (ptxas never auto-emits FFMA2) ----
__device__ __forceinline__ u64 fma2(u64 a, u64 b, u64 c) {
    u64 d; asm("fma.rn.f32x2 %0, %1, %2, %3;" : "=l"(d) : "l"(a), "l"(b), "l"(c)); return d;
}
__device__ __forceinline__ u64 packf2(float lo, float hi) {
    u64 d; asm("mov.b64 %0, {%1, %2};" : "=l"(d) : "f"(lo), "f"(hi)); return d;
}
__device__ __forceinline__ float2 unpackf2(u64 v) {
    float2 f; asm("mov.b64 {%0, %1}, %2;" : "=f"(f.x), "=f"(f.y) : "l"(v)); return f;
}
// 16B shared load straight into two 64-bit regs
__device__ __forceinline__ void lds2(u64 &a, u64 &b, uint32_t addr) {
    asm volatile("ld.shared.v2.b64 {%0, %1}, [%2];" : "=l"(a), "=l"(b) : "r"(addr));
}

__device__ __forceinline__ float sigf(float x) {
    float e = __expf(-x);
    return __fdividef(1.0f, 1.0f + e);
}
__device__ __forceinline__ float tanhf_(float x) {
    float ax = fabsf(x);
    float e = __expf(-2.0f * ax);
    float r = __fdividef(1.0f - e, 1.0f + e);
    return copysignf(r, x);
}

// ============================================================================
// Fused 2-layer LSTM. One CTA per 2 sequences, 256 threads.
// Thread j owns gate row j of Whh0, Wih1, Whh1 (all in registers).
// Software pipeline: iteration t computes layer1 step t and layer2 step t-1.
//   sh1 holds h1[t-1] (used by BOTH l1 recurrence and l2 input GEMV),
//   sh2 holds h2[t-2].
// Cell phase: 256 threads = 256 cells (2 layers x 2 seqs x 64).
// ============================================================================
__global__ void __launch_bounds__(256, 1) lstm_fused(
    const float* __restrict__ x,
    const float* __restrict__ Wih0, const float* __restrict__ Whh0,
    const float* __restrict__ bih0, const float* __restrict__ bhh0,
    const float* __restrict__ Wih1, const float* __restrict__ Whh1,
    const float* __restrict__ bih1, const float* __restrict__ bhh1)
{
    __shared__ __align__(16) float sx[2][TSTEPS * DIN];  // 24 KB
    __shared__ __align__(16) float sh1[2][HID];
    __shared__ __align__(16) float sh2[2][HID];
    __shared__ __align__(16) float sg1[2][256];
    __shared__ __align__(16) float sg2[2][256];
    const int tid = threadIdx.x;
    const int b0 = blockIdx.x * 2;

    // stage both sequences' inputs
    {
        const float4* xs0 = (const float4*)(x + (size_t)b0 * TSTEPS * DIN);
        const float4* xs1 = (const float4*)(x + (size_t)(b0 + 1) * TSTEPS * DIN);
        #pragma unroll
        for (int i = 0; i < 3; i++) {
            int idx = tid + i * 256;
            ((float4*)sx[0])[idx] = xs0[idx];
            ((float4*)sx[1])[idx] = xs1[idx];
        }
    }

    // per-thread weight rows, packed f32x2 along k
    u64 w0[32], wA[32], wB[32];
    {
        const float4* r0 = (const float4*)(Whh0 + tid * HID);
        const float4* rA = (const float4*)(Wih1 + tid * HID);
        const float4* rB = (const float4*)(Whh1 + tid * HID);
        #pragma unroll
        for (int i = 0; i < 16; i++) {
            float4 v = r0[i]; w0[2*i] = packf2(v.x, v.y); w0[2*i+1] = packf2(v.z, v.w);
            float4 a = rA[i]; wA[2*i] = packf2(a.x, a.y); wA[2*i+1] = packf2(a.z, a.w);
            float4 b = rB[i]; wB[2*i] = packf2(b.x, b.y); wB[2*i+1] = packf2(b.z, b.w);
        }
    }
    const float wx0 = Wih0[tid * 3 + 0], wx1 = Wih0[tid * 3 + 1], wx2 = Wih0[tid * 3 + 2];
    const float bias0 = bih0[tid] + bhh0[tid];
    const float bias1 = bih1[tid] + bhh1[tid];
    const int gtype = tid >> 6;

    // cell role: tid -> (layer, seq, m)
    const int cl_layer = tid >> 7;
    const int cl_b = (tid >> 6) & 1;
    const int cl_m = tid & 63;
    float c = 0.0f;

    if (tid < 128) ((float*)sh1)[tid] = 0.0f;
    else           ((float*)sh2)[tid - 128] = 0.0f;

    const uint32_t a_h1s0 = (uint32_t)__cvta_generic_to_shared(&sh1[0][0]);
    const uint32_t a_h1s1 = (uint32_t)__cvta_generic_to_shared(&sh1[1][0]);
    const uint32_t a_h2s0 = (uint32_t)__cvta_generic_to_shared(&sh2[0][0]);
    const uint32_t a_h2s1 = (uint32_t)__cvta_generic_to_shared(&sh2[1][0]);
    float* h2out = &g_h2[(size_t)(b0 + cl_b) * TSTEPS * HID + cl_m];
    __syncthreads();

    #pragma unroll 1
    for (int t = 0; t <= TSTEPS; t++) {
        // ---- gate phase: 6 dot products, 192 fma2, 64 LDS.128 (all broadcast)
        u64 A0 = 0, A1 = 0, B0 = 0, B1 = 0, C0 = 0, C1 = 0;
        #pragma unroll
        for (int kk = 0; kk < 16; kk++) {
            u64 p0, p1, q0, q1, r0, r1, s0, s1;
            lds2(p0, p1, a_h1s0 + kk * 16);
            lds2(q0, q1, a_h1s1 + kk * 16);
            lds2(r0, r1, a_h2s0 + kk * 16);
            lds2(s0, s1, a_h2s1 + kk * 16);
            A0 = fma2(w0[2*kk], p0, A0); A0 = fma2(w0[2*kk+1], p1, A0);
            A1 = fma2(w0[2*kk], q0, A1); A1 = fma2(w0[2*kk+1], q1, A1);
            B0 = fma2(wA[2*kk], p0, B0); B0 = fma2(wA[2*kk+1], p1, B0);
            B1 = fma2(wA[2*kk], q0, B1); B1 = fma2(wA[2*kk+1], q1, B1);
            C0 = fma2(wB[2*kk], r0, C0); C0 = fma2(wB[2*kk+1], r1, C0);
            C1 = fma2(wB[2*kk], s0, C1); C1 = fma2(wB[2*kk+1], s1, C1);
        }
        const int tx = (t < TSTEPS) ? t : (TSTEPS - 1);
        float xa0 = sx[0][tx*3+0], xa1 = sx[0][tx*3+1], xa2 = sx[0][tx*3+2];
        float xb0 = sx[1][tx*3+0], xb1 = sx[1][tx*3+1], xb2 = sx[1][tx*3+2];
        float2 fA0 = unpackf2(A0), fA1 = unpackf2(A1);
        float2 fB0 = unpackf2(B0), fB1 = unpackf2(B1);
        float2 fC0 = unpackf2(C0), fC1 = unpackf2(C1);
        float pre10 = fA0.x + fA0.y + bias0 + wx0*xa0 + wx1*xa1 + wx2*xa2;
        float pre11 = fA1.x + fA1.y + bias0 + wx0*xb0 + wx1*xb1 + wx2*xb2;
        float pre20 = (fB0.x + fB0.y) + (fC0.x + fC0.y) + bias1;
        float pre21 = (fB1.x + fB1.y) + (fC1.x + fC1.y) + bias1;
        float v10, v11, v20, v21;
        if (gtype == 2) {
            v10 = tanhf_(pre10); v11 = tanhf_(pre11);
            v20 = tanhf_(pre20); v21 = tanhf_(pre21);
        } else {
            v10 = sigf(pre10); v11 = sigf(pre11);
            v20 = sigf(pre20); v21 = sigf(pre21);
        }
        sg1[0][tid] = v10; sg1[1][tid] = v11;
        sg2[0][tid] = v20; sg2[1][tid] = v21;
        __syncthreads();

        // ---- cell phase: one cell per thread (warp-uniform roles)
        bool active = cl_layer ? (t >= 1) : (t < TSTEPS);
        if (active) {
            const float* Gp = cl_layer ? sg2[cl_b] : sg1[cl_b];
            float iv = Gp[cl_m], fv = Gp[cl_m + 64];
            float gv = Gp[cl_m + 128], ov = Gp[cl_m + 192];
            c = fv * c + iv * gv;
            float hn = ov * tanhf_(c);
            if (cl_layer) {
                sh2[cl_b][cl_m] = hn;
                h2out[(size_t)(t - 1) * HID] = hn;
            } else {
                sh1[cl_b][cl_m] = hn;
            }
        }
        __syncthreads();
    }
}

// ============================================================================
// Output projection: y[r, 0..2] = W_out · h2[r] + b_out.
// ============================================================================
__global__ void __launch_bounds__(256) proj_kernel(
    const float* __restrict__ Wout, const float* __restrict__ bout,
    float* __restrict__ y)
{
    __shared__ float sw[3 * 64];
    __shared__ float sb[3];
    const int tid = threadIdx.x;
    if (tid < 192) sw[tid] = Wout[tid];
    if (tid < 3)   sb[tid] = bout[tid];
    __syncthreads();

    int g = blockIdx.x * 256 + tid;
    int r = g >> 4;
    int seg = g & 15;
    float4 v = *(const float4*)&g_h2[(size_t)r * HID + seg * 4];
    int s4 = seg * 4;
    float a0 = sw[s4] * v.x + sw[s4+1] * v.y + sw[s4+2] * v.z + sw[s4+3] * v.w;
    float a1 = sw[64+s4] * v.x + sw[64+s4+1] * v.y + sw[64+s4+2] * v.z + sw[64+s4+3] * v.w;
    float a2 = sw[128+s4] * v.x + sw[128+s4+1] * v.y + sw[128+s4+2] * v.z + sw[128+s4+3] * v.w;
    #pragma unroll
    for (int o = 8; o > 0; o >>= 1) {
        a0 += __shfl_xor_sync(0xffffffffu, a0, o);
        a1 += __shfl_xor_sync(0xffffffffu, a1, o);
        a2 += __shfl_xor_sync(0xffffffffu, a2, o);
    }
    if (seg == 0) {
        y[(size_t)r * 3 + 0] = a0 + sb[0];
        y[(size_t)r * 3 + 1] = a1 + sb[1];
        y[(size_t)r * 3 + 2] = a2 + sb[2];
    }
}

extern "C" void kernel_launch(void* const* d_in, const int* in_sizes, int n_in,
                              void* d_out, int out_size)
{
    const float* x    = (const float*)d_in[0];
    const float* Wih0 = (const float*)d_in[1];
    const float* Whh0 = (const float*)d_in[2];
    const float* bih0 = (const float*)d_in[3];
    const float* bhh0 = (const float*)d_in[4];
    const float* Wih1 = (const float*)d_in[5];
    const float* Whh1 = (const float*)d_in[6];
    const float* bih1 = (const float*)d_in[7];
    const float* bhh1 = (const float*)d_in[8];
    const float* Wout = (const float*)d_in[9];
    const float* bout = (const float*)d_in[10];
    float* y = (float*)d_out;

    lstm_fused<<<BATCH / 2, 256>>>(x, Wih0, Whh0, bih0, bhh0,
                                   Wih1, Whh1, bih1, bhh1);
    proj_kernel<<<(BATCH * TSTEPS * 16) / 256, 256>>>(Wout, bout, y);
}